// round 1
// baseline (speedup 1.0000x reference)
#include <cuda_runtime.h>
#include <math.h>

// Problem constants
#define E   4096
#define BB  8          // batch
#define TJ  512        // columns per block in K1 (128 threads * float4)
#define TK  64         // rows per split in K1
#define NSPLIT (E / TK)   // 64 row-splits
#define NCOLB  (E / TJ)   // 8 column blocks

// Deterministic split-K scratch: [NSPLIT][BB][E] fp32 = 8 MB
__device__ float g_scratch[(size_t)NSPLIT * BB * E];

// ---------------------------------------------------------------------------
// K1: stream w/alpha/hebb once (192 MB). Each block: 64 rows x 512 cols.
// acc[b][c] += yin[b,k] * (w[k,j] + alpha[k,j]*hebb[k,j])
// Partials written to g_scratch[split][b][j]  (no atomics -> deterministic).
// ---------------------------------------------------------------------------
__global__ __launch_bounds__(128)
void k1_partial_gemm(const float* __restrict__ yin,
                     const float* __restrict__ hebb,
                     const float* __restrict__ w,
                     const float* __restrict__ alpha)
{
    const int cb  = blockIdx.x;            // 0..NCOLB-1
    const int rb  = blockIdx.y;            // 0..NSPLIT-1
    const int tid = threadIdx.x;           // 0..127
    const int j0  = cb * TJ + tid * 4;     // this thread's 4 columns
    const int k0  = rb * TK;

    // Stage yin[b, k0:k0+TK] in smem (broadcast reuse across 128 threads)
    __shared__ float yin_s[BB][TK];
    for (int i = tid; i < BB * TK; i += 128) {
        int b = i / TK, k = i % TK;
        yin_s[b][k] = yin[(size_t)b * E + k0 + k];
    }
    __syncthreads();

    float acc[BB][4];
#pragma unroll
    for (int b = 0; b < BB; b++) {
        acc[b][0] = 0.f; acc[b][1] = 0.f; acc[b][2] = 0.f; acc[b][3] = 0.f;
    }

#pragma unroll 4
    for (int k = 0; k < TK; k++) {
        const size_t base = (size_t)(k0 + k) * E + j0;
        const float4 w4 = *(const float4*)(w     + base);
        const float4 a4 = *(const float4*)(alpha + base);
        const float4 h4 = *(const float4*)(hebb  + base);
        float4 m;
        m.x = fmaf(a4.x, h4.x, w4.x);
        m.y = fmaf(a4.y, h4.y, w4.y);
        m.z = fmaf(a4.z, h4.z, w4.z);
        m.w = fmaf(a4.w, h4.w, w4.w);
#pragma unroll
        for (int b = 0; b < BB; b++) {
            const float yv = yin_s[b][k];
            acc[b][0] = fmaf(yv, m.x, acc[b][0]);
            acc[b][1] = fmaf(yv, m.y, acc[b][1]);
            acc[b][2] = fmaf(yv, m.z, acc[b][2]);
            acc[b][3] = fmaf(yv, m.w, acc[b][3]);
        }
    }

#pragma unroll
    for (int b = 0; b < BB; b++) {
        float4 v = make_float4(acc[b][0], acc[b][1], acc[b][2], acc[b][3]);
        *(float4*)(g_scratch + ((size_t)rb * BB + b) * E + j0) = v;
    }
}

// ---------------------------------------------------------------------------
// K2: reduce splits + input, tanh -> yout (written to d_out[0 : BB*E])
// ---------------------------------------------------------------------------
__global__ __launch_bounds__(256)
void k2_yout(const float* __restrict__ input, float* __restrict__ yout)
{
    const int idx = blockIdx.x * 256 + threadIdx.x;  // 0 .. BB*E-1
    if (idx >= BB * E) return;
    float s = input[idx];
#pragma unroll
    for (int r = 0; r < NSPLIT; r++)
        s += g_scratch[(size_t)r * BB * E + idx];
    yout[idx] = tanhf(s);
}

// ---------------------------------------------------------------------------
// K3: hebb_new = (1-eta)*hebb + eta * yin0 (outer) yout0   (128 MB stream)
// ---------------------------------------------------------------------------
__global__ __launch_bounds__(256)
void k3_hebb(const float* __restrict__ hebb,
             const float* __restrict__ yin,    // row 0 used
             const float* __restrict__ eta,    // scalar
             const float* __restrict__ yout0,  // d_out row 0 (E floats)
             float* __restrict__ hebb_out)
{
    const float et    = eta[0];
    const float one_m = 1.0f - et;

    const int t = blockIdx.x * 256 + threadIdx.x;     // one float4 per thread
    const int n4 = (E * E) / 4;
    if (t >= n4) return;

    const int row = t / (E / 4);
    const int c4  = t % (E / 4);
    const float s = et * yin[row];                    // eta * yin0[row]

    const float4 h = *(const float4*)(hebb  + (size_t)t * 4);
    const float4 y = *(const float4*)(yout0 + (size_t)c4 * 4);
    float4 o;
    o.x = fmaf(one_m, h.x, s * y.x);
    o.y = fmaf(one_m, h.y, s * y.y);
    o.z = fmaf(one_m, h.z, s * y.z);
    o.w = fmaf(one_m, h.w, s * y.w);
    *(float4*)(hebb_out + (size_t)t * 4) = o;
}

// ---------------------------------------------------------------------------
// Launch: inputs in metadata order: input, yin, hebb, w, alpha, eta
// Output: [yout (8*4096) | hebb_new (4096*4096)] fp32
// ---------------------------------------------------------------------------
extern "C" void kernel_launch(void* const* d_in, const int* in_sizes, int n_in,
                              void* d_out, int out_size)
{
    const float* input = (const float*)d_in[0];
    const float* yin   = (const float*)d_in[1];
    const float* hebb  = (const float*)d_in[2];
    const float* w     = (const float*)d_in[3];
    const float* alpha = (const float*)d_in[4];
    const float* eta   = (const float*)d_in[5];

    float* out      = (float*)d_out;
    float* yout     = out;            // BB*E
    float* hebb_out = out + BB * E;   // E*E

    // K1: 8 col-blocks x 64 row-splits = 512 blocks
    dim3 g1(NCOLB, NSPLIT);
    k1_partial_gemm<<<g1, 128>>>(yin, hebb, w, alpha);

    // K2: 32768 elems
    k2_yout<<<(BB * E + 255) / 256, 256>>>(input, yout);

    // K3: E*E/4 float4 threads
    const int n4 = (E * E) / 4;
    k3_hebb<<<(n4 + 255) / 256, 256>>>(hebb, yin, eta, yout, hebb_out);
}